// round 15
// baseline (speedup 1.0000x reference)
#include <cuda_runtime.h>
#include <math_constants.h>

#define BN     8
#define BC     256
#define BNF    16
#define BWH    784           // 28*28
#define CSTR4  3136          // float4 stride between channels of l
#define NV4    196           // float4 per wh-row
#define NTILE  (BN*BNF)      // 128
#define NCH1   7             // K1 wh-chunks per tile (uniform 28 f4)
#define CH4    28            // f4 per K1 chunk
#define NCH2   8             // K2 channel-chunks per tile (32 channels)
#define NK1    (NTILE*NCH1)  // 896 producer blocks
#define NK2    (NTILE*NCH2)  // 1024 consumer blocks
#define NTHR   256

// monotonic counters — never reset, replay-safe
__device__ unsigned int d_arr[NTILE];    // K1 chunk completions (7 per tile per launch)
__device__ unsigned int d_k2c[NTILE];    // K2 arrivals (8 per tile per launch) -> epoch

__global__ __launch_bounds__(NTHR)
void mfla_fused(const float* __restrict__ l,
                const float* __restrict__ g,
                const float* __restrict__ w,
                float* __restrict__ outc,   // [N,NF,W,H]
                float* __restrict__ outg)   // [N,C,NF]
{
    __shared__ float sw[BC];
    __shared__ __align__(16) float4 part[8][CH4];
    __shared__ __align__(16) float sc[BWH];
    __shared__ float red[8];
    __shared__ float s_gdot, s_inv;
    __shared__ unsigned int s_target;

    const int tid = threadIdx.x;
    const int bid = blockIdx.x;

    if (bid < NK1) {
        // ================= K1 role: c-map chunk =================
        const int tile = bid / NCH1;
        const int j    = bid - tile * NCH1;
        const int n    = tile >> 4;
        const int f    = tile & 15;
        const int start4 = j * CH4;

        const float4* lb4 = reinterpret_cast<const float4*>(
            l + ((size_t)n * BC * BNF + f) * BWH);

        // weights + gdot
        float wv = w[tid];
        sw[tid] = wv;
        float p = g[n * BC + tid] * wv;
        #pragma unroll
        for (int o = 16; o; o >>= 1) p += __shfl_xor_sync(0xffffffffu, p, o);
        if ((tid & 31) == 0) red[tid >> 5] = p;
        __syncthreads();
        if (tid < 8) {
            float v = red[tid];
            #pragma unroll
            for (int o = 4; o; o >>= 1) v += __shfl_xor_sync(0xffu, v, o);
            if (tid == 0) s_gdot = v;
        }

        // channel dot: 8 warps x 32 channels; lanes 0..27 = wh4 slots
        {
            const int gq = tid >> 5;
            const int s  = tid & 31;
            if (s < CH4) {
                const float4* lp = lb4 + (size_t)(gq * 32) * CSTR4 + start4 + s;
                float4 a = make_float4(0.f, 0.f, 0.f, 0.f);
                #pragma unroll
                for (int c = 0; c < 32; ++c) {
                    float4 v = lp[(size_t)c * CSTR4];
                    float  ww = sw[gq * 32 + c];
                    a.x = fmaf(v.x, ww, a.x);
                    a.y = fmaf(v.y, ww, a.y);
                    a.z = fmaf(v.z, ww, a.z);
                    a.w = fmaf(v.w, ww, a.w);
                }
                part[gq][s] = a;
            }
        }
        __syncthreads();

        if (tid < CH4) {
            const float gd = s_gdot;
            float4 v = make_float4(gd, gd, gd, gd);
            #pragma unroll
            for (int k = 0; k < 8; ++k) {
                float4 q = part[k][tid];
                v.x += q.x; v.y += q.y; v.z += q.z; v.w += q.w;
            }
            reinterpret_cast<float4*>(outc)[(size_t)tile * NV4 + start4 + tid] = v;
        }
        __threadfence();               // release outc chunk
        __syncthreads();
        if (tid == 0) atomicAdd(&d_arr[tile], 1u);

    } else {
        // ================= K2 role: softmax + pool 32 channels =================
        const int bid2 = bid - NK1;
        const int tile = bid2 >> 3;
        const int cc   = bid2 & 7;
        const int n    = tile >> 4;
        const int f    = tile & 15;

        // epoch from my own monotonic counter; wait for this launch's 7 producers
        if (tid == 0) {
            unsigned int old = atomicAdd(&d_k2c[tile], 1u);
            unsigned int target = (old / NCH2 + 1u) * NCH1;
            while (atomicAdd(&d_arr[tile], 0u) < target) __nanosleep(64);
            s_target = 1u;   // (kept to prevent compiler elision)
        }
        __syncthreads();
        __threadfence();               // acquire producers' outc writes

        // exp + partial sum (bypass L1 for outc)
        float se = 0.f;
        if (tid < NV4) {
            float4 c4 = __ldcg(reinterpret_cast<const float4*>(outc) + (size_t)tile * NV4 + tid);
            float4 e4 = make_float4(__expf(c4.x), __expf(c4.y), __expf(c4.z), __expf(c4.w));
            reinterpret_cast<float4*>(sc)[tid] = e4;
            se = (e4.x + e4.y) + (e4.z + e4.w);
        }
        #pragma unroll
        for (int o = 16; o; o >>= 1) se += __shfl_xor_sync(0xffffffffu, se, o);
        if ((tid & 31) == 0) red[tid >> 5] = se;
        __syncthreads();
        if (tid < 8) {
            float v = red[tid];
            #pragma unroll
            for (int o = 4; o; o >>= 1) v += __shfl_xor_sync(0xffu, v, o);
            if (tid == 0) s_inv = 1.0f / v;
        }
        __syncthreads();

        // pool: 8 warps x 4 channels (R9 shape)
        {
            const int warp = tid >> 5;
            const int lane = tid & 31;
            const int c0   = 32 * cc + 4 * warp;
            const float inv = s_inv;
            const float4* av = reinterpret_cast<const float4*>(sc);
            const float4* lv = reinterpret_cast<const float4*>(
                l + ((size_t)(n * BC + c0) * BNF + f) * BWH);
            float acc[4] = {0.f, 0.f, 0.f, 0.f};
            for (int i = lane; i < NV4; i += 32) {
                float4 a4 = av[i];
                #pragma unroll
                for (int k = 0; k < 4; ++k) {
                    float4 l4 = lv[(size_t)k * CSTR4 + i];
                    acc[k] += a4.x * l4.x + a4.y * l4.y + a4.z * l4.z + a4.w * l4.w;
                }
            }
            #pragma unroll
            for (int k = 0; k < 4; ++k) {
                float a = acc[k];
                #pragma unroll
                for (int o = 16; o; o >>= 1) a += __shfl_xor_sync(0xffffffffu, a, o);
                if (lane == 0)
                    outg[((size_t)n * BC + c0 + k) * BNF + f] = a * inv;
            }
        }
    }
}

extern "C" void kernel_launch(void* const* d_in, const int* in_sizes, int n_in,
                              void* d_out, int out_size)
{
    const float* l = (const float*)d_in[0];
    const float* g = (const float*)d_in[1];
    const float* w = (const float*)d_in[2];
    float* out  = (float*)d_out;
    float* outc = out;                              // 8*16*28*28 = 100352 floats
    float* outg = out + (size_t)BN * BNF * BWH;     // 8*256*16   = 32768 floats

    mfla_fused<<<NK1 + NK2, NTHR>>>(l, g, w, outc, outg);
}

// round 16
// speedup vs baseline: 1.1511x; 1.1511x over previous
#include <cuda_runtime.h>
#include <math_constants.h>

#define BN     8
#define BC     256
#define BNF    16
#define BWH    784           // 28*28
#define CSTR4  3136          // float4 stride between channels of l
#define NV4    196           // float4 per wh-row
#define NTILE  (BN*BNF)      // 128
#define NCH1   7             // K1 wh-chunks per tile (uniform 28 f4)
#define CH4    28
#define NCH2   8             // K2 channel-chunks per tile
#define K1THR  256
#define K2THR  256

// ---------------- K1: c[n,f,wh] = sum_c (l+g)·w over a 28-f4 chunk ----------------
__global__ __launch_bounds__(K1THR)
void mfla_c_kernel(const float* __restrict__ l,
                   const float* __restrict__ g,
                   const float* __restrict__ w,
                   float* __restrict__ outc)
{
    __shared__ float sw[BC];
    __shared__ __align__(16) float4 part[8][CH4];
    __shared__ float red[8];
    __shared__ float s_gdot;

    const int tid  = threadIdx.x;
    const int tile = blockIdx.x / NCH1;     // n*16 + f
    const int j    = blockIdx.x - tile * NCH1;
    const int n    = tile >> 4;
    const int f    = tile & 15;
    const int start4 = j * CH4;

    const float4* lb4 = reinterpret_cast<const float4*>(
        l + ((size_t)n * BC * BNF + f) * BWH);

    // weights + gdot
    float wv = w[tid];
    sw[tid] = wv;
    float p = g[n * BC + tid] * wv;
    #pragma unroll
    for (int o = 16; o; o >>= 1) p += __shfl_xor_sync(0xffffffffu, p, o);
    if ((tid & 31) == 0) red[tid >> 5] = p;
    __syncthreads();
    if (tid < 8) {
        float v = red[tid];
        #pragma unroll
        for (int o = 4; o; o >>= 1) v += __shfl_xor_sync(0xffu, v, o);
        if (tid == 0) s_gdot = v;
    }

    // channel dot: 8 warps x 32 channels; lanes 0..27 = wh4 slots
    {
        const int gq = tid >> 5;
        const int s  = tid & 31;
        if (s < CH4) {
            const float4* lp = lb4 + (size_t)(gq * 32) * CSTR4 + start4 + s;
            float4 a = make_float4(0.f, 0.f, 0.f, 0.f);
            #pragma unroll
            for (int c = 0; c < 32; ++c) {
                float4 v = lp[(size_t)c * CSTR4];
                float  ww = sw[gq * 32 + c];
                a.x = fmaf(v.x, ww, a.x);
                a.y = fmaf(v.y, ww, a.y);
                a.z = fmaf(v.z, ww, a.z);
                a.w = fmaf(v.w, ww, a.w);
            }
            part[gq][s] = a;
        }
    }
    __syncthreads();

    if (tid < CH4) {
        const float gd = s_gdot;
        float4 v = make_float4(gd, gd, gd, gd);
        #pragma unroll
        for (int k = 0; k < 8; ++k) {
            float4 q = part[k][tid];
            v.x += q.x; v.y += q.y; v.z += q.z; v.w += q.w;
        }
        reinterpret_cast<float4*>(outc)[(size_t)tile * NV4 + start4 + tid] = v;
    }

    // signal: this block's contribution to the dependent launch is done
    cudaTriggerProgrammaticLaunchCompletion();
}

// ---------------- K2: softmax + pool 32 channels (R9 shape, PDL-gated) ----------------
__global__ __launch_bounds__(K2THR)
void mfla_pool_kernel(const float* __restrict__ l,
                      const float* __restrict__ outc,
                      float* __restrict__ outg)
{
    __shared__ __align__(16) float sc[BWH];
    __shared__ float red[8];
    __shared__ float s_inv;

    const int tid  = threadIdx.x;
    const int tile = blockIdx.x >> 3;      // n*16 + f
    const int cc   = blockIdx.x & 7;       // channels [32cc, 32cc+32)
    const int n    = tile >> 4;
    const int f    = tile & 15;

    // wait for K1's outc writes to be visible
    cudaGridDependencySynchronize();

    // exp + partial sum
    float se = 0.f;
    if (tid < NV4) {
        float4 c4 = __ldcg(reinterpret_cast<const float4*>(outc) + (size_t)tile * NV4 + tid);
        float4 e4 = make_float4(__expf(c4.x), __expf(c4.y), __expf(c4.z), __expf(c4.w));
        reinterpret_cast<float4*>(sc)[tid] = e4;
        se = (e4.x + e4.y) + (e4.z + e4.w);
    }
    #pragma unroll
    for (int o = 16; o; o >>= 1) se += __shfl_xor_sync(0xffffffffu, se, o);
    if ((tid & 31) == 0) red[tid >> 5] = se;
    __syncthreads();
    if (tid < 8) {
        float v = red[tid];
        #pragma unroll
        for (int o = 4; o; o >>= 1) v += __shfl_xor_sync(0xffu, v, o);
        if (tid == 0) s_inv = 1.0f / v;
    }
    __syncthreads();

    // pool: 8 warps x 4 channels
    {
        const int warp = tid >> 5;
        const int lane = tid & 31;
        const int c0   = 32 * cc + 4 * warp;
        const float inv = s_inv;
        const float4* av = reinterpret_cast<const float4*>(sc);
        const float4* lv = reinterpret_cast<const float4*>(
            l + ((size_t)(n * BC + c0) * BNF + f) * BWH);
        float acc[4] = {0.f, 0.f, 0.f, 0.f};
        for (int i = lane; i < NV4; i += 32) {
            float4 a4 = av[i];
            #pragma unroll
            for (int k = 0; k < 4; ++k) {
                float4 l4 = lv[(size_t)k * CSTR4 + i];
                acc[k] += a4.x * l4.x + a4.y * l4.y + a4.z * l4.z + a4.w * l4.w;
            }
        }
        #pragma unroll
        for (int k = 0; k < 4; ++k) {
            float a = acc[k];
            #pragma unroll
            for (int o = 16; o; o >>= 1) a += __shfl_xor_sync(0xffffffffu, a, o);
            if (lane == 0)
                outg[((size_t)n * BC + c0 + k) * BNF + f] = a * inv;
        }
    }
}

extern "C" void kernel_launch(void* const* d_in, const int* in_sizes, int n_in,
                              void* d_out, int out_size)
{
    const float* l = (const float*)d_in[0];
    const float* g = (const float*)d_in[1];
    const float* w = (const float*)d_in[2];
    float* out  = (float*)d_out;
    float* outc = out;                              // 8*16*28*28 = 100352 floats
    float* outg = out + (size_t)BN * BNF * BWH;     // 8*256*16   = 32768 floats

    // K1: normal launch
    mfla_c_kernel<<<NTILE * NCH1, K1THR>>>(l, g, w, outc);

    // K2: programmatic dependent launch — overlaps K1's tail
    cudaLaunchConfig_t cfg = {};
    cfg.gridDim  = dim3(NTILE * NCH2, 1, 1);
    cfg.blockDim = dim3(K2THR, 1, 1);
    cudaLaunchAttribute attr[1];
    attr[0].id = cudaLaunchAttributeProgrammaticStreamSerialization;
    attr[0].val.programmaticStreamSerializationAllowed = 1;
    cfg.attrs = attr;
    cfg.numAttrs = 1;
    cudaLaunchKernelEx(&cfg, mfla_pool_kernel, l, (const float*)outc, outg);
}

// round 17
// speedup vs baseline: 1.4863x; 1.2912x over previous
#include <cuda_runtime.h>
#include <math_constants.h>

#define BN    8
#define BC    256
#define BNF   16
#define BWH   784            // 28*28
#define CSTR4 3136           // float4 stride between channels of l
#define NV4   196            // float4 per wh-row
#define NCHUNK 8             // wh-chunks (K1) / channel-chunks (K2) per tile
#define K1THR 256
#define K2THR 256

// ---------------- K1: c[n,f,wh] = sum_c (l+g)·w  over a wh-chunk ----------------
// chunk geometry, 128B-line aligned per f-parity:
//   even f: j<7 -> (24j,24), j=7 -> (168,28);  odd f: j=0 -> (0,28), j>0 -> (24j+4,24)
__global__ __launch_bounds__(K1THR)
void mfla_c_kernel(const float* __restrict__ l,
                   const float* __restrict__ g,
                   const float* __restrict__ w,
                   float* __restrict__ outc)
{
    __shared__ float sw[BC];
    __shared__ __align__(16) float4 part[8][28];
    __shared__ float red[8];
    __shared__ float s_gdot;

    const int tid  = threadIdx.x;
    const int tile = blockIdx.x >> 3;      // n*16 + f
    const int j    = blockIdx.x & 7;
    const int n    = tile >> 4;
    const int f    = tile & 15;

    int start4, len4;
    if ((f & 1) == 0) { start4 = (j < 7) ? 24 * j : 168;     len4 = (j < 7) ? 24 : 28; }
    else              { start4 = (j == 0) ? 0 : 24 * j + 4;  len4 = (j == 0) ? 28 : 24; }

    const float4* lb4 = reinterpret_cast<const float4*>(
        l + ((size_t)n * BC * BNF + f) * BWH);

    // weights + gdot
    float wv = w[tid];
    sw[tid] = wv;
    float p = g[n * BC + tid] * wv;
    #pragma unroll
    for (int o = 16; o; o >>= 1) p += __shfl_xor_sync(0xffffffffu, p, o);
    if ((tid & 31) == 0) red[tid >> 5] = p;
    __syncthreads();
    if (tid < 8) {
        float v = red[tid];
        #pragma unroll
        for (int o = 4; o; o >>= 1) v += __shfl_xor_sync(0xffu, v, o);
        if (tid == 0) s_gdot = v;
    }

    // channel dot: 8 warps x 32 channels; lane = wh4 slot within chunk
    {
        const int gq = tid >> 5;
        const int s  = tid & 31;
        if (s < len4) {
            const float4* lp = lb4 + (size_t)(gq * 32) * CSTR4 + start4 + s;
            float4 a = make_float4(0.f, 0.f, 0.f, 0.f);
            #pragma unroll
            for (int c = 0; c < 32; ++c) {
                float4 v = lp[(size_t)c * CSTR4];
                float  ww = sw[gq * 32 + c];
                a.x = fmaf(v.x, ww, a.x);
                a.y = fmaf(v.y, ww, a.y);
                a.z = fmaf(v.z, ww, a.z);
                a.w = fmaf(v.w, ww, a.w);
            }
            part[gq][s] = a;
        }
    }
    __syncthreads();

    if (tid < len4) {
        const float gd = s_gdot;
        float4 v = make_float4(gd, gd, gd, gd);
        #pragma unroll
        for (int k = 0; k < 8; ++k) {
            float4 q = part[k][tid];
            v.x += q.x; v.y += q.y; v.z += q.z; v.w += q.w;
        }
        reinterpret_cast<float4*>(outc)[(size_t)tile * NV4 + start4 + tid] = v;
    }
}

// ---------------- K2: softmax over wh (per tile) + pool 32 channels ----------------
__global__ __launch_bounds__(K2THR)
void mfla_pool_kernel(const float* __restrict__ l,
                      const float* __restrict__ outc,
                      float* __restrict__ outg)
{
    __shared__ __align__(16) float sc[BWH];   // exp values
    __shared__ float red[8];
    __shared__ float s_inv;

    const int tid  = threadIdx.x;
    const int tile = blockIdx.x >> 3;      // n*16 + f
    const int cc   = blockIdx.x & 7;       // channels [32cc, 32cc+32)
    const int n    = tile >> 4;
    const int f    = tile & 15;

    // exp + partial sum (outc was just written by K1 -> L2; skip L1 probe)
    float se = 0.f;
    if (tid < NV4) {
        float4 c4 = __ldcg(reinterpret_cast<const float4*>(outc) + (size_t)tile * NV4 + tid);
        float4 e4 = make_float4(__expf(c4.x), __expf(c4.y), __expf(c4.z), __expf(c4.w));
        reinterpret_cast<float4*>(sc)[tid] = e4;
        se = (e4.x + e4.y) + (e4.z + e4.w);
    }
    #pragma unroll
    for (int o = 16; o; o >>= 1) se += __shfl_xor_sync(0xffffffffu, se, o);
    if ((tid & 31) == 0) red[tid >> 5] = se;
    __syncthreads();
    if (tid < 8) {
        float v = red[tid];
        #pragma unroll
        for (int o = 4; o; o >>= 1) v += __shfl_xor_sync(0xffu, v, o);
        if (tid == 0) s_inv = 1.0f / v;
    }
    __syncthreads();

    // pool: 8 warps x 4 channels each (streaming loads: each value used once)
    {
        const int warp = tid >> 5;
        const int lane = tid & 31;
        const int c0   = 32 * cc + 4 * warp;
        const float inv = s_inv;
        const float4* av = reinterpret_cast<const float4*>(sc);
        const float4* lv = reinterpret_cast<const float4*>(
            l + ((size_t)(n * BC + c0) * BNF + f) * BWH);
        float acc[4] = {0.f, 0.f, 0.f, 0.f};
        for (int i = lane; i < NV4; i += 32) {
            float4 a4 = av[i];
            #pragma unroll
            for (int k = 0; k < 4; ++k) {
                float4 l4 = __ldcs(lv + (size_t)k * CSTR4 + i);
                acc[k] += a4.x * l4.x + a4.y * l4.y + a4.z * l4.z + a4.w * l4.w;
            }
        }
        #pragma unroll
        for (int k = 0; k < 4; ++k) {
            float a = acc[k];
            #pragma unroll
            for (int o = 16; o; o >>= 1) a += __shfl_xor_sync(0xffffffffu, a, o);
            if (lane == 0)
                outg[((size_t)n * BC + c0 + k) * BNF + f] = a * inv;
        }
    }
}

extern "C" void kernel_launch(void* const* d_in, const int* in_sizes, int n_in,
                              void* d_out, int out_size)
{
    const float* l = (const float*)d_in[0];
    const float* g = (const float*)d_in[1];
    const float* w = (const float*)d_in[2];
    float* out  = (float*)d_out;
    float* outc = out;                              // 8*16*28*28 = 100352 floats
    float* outg = out + (size_t)BN * BNF * BWH;     // 8*256*16   = 32768 floats

    mfla_c_kernel   <<<BN * BNF * NCHUNK, K1THR>>>(l, g, w, outc);
    mfla_pool_kernel<<<BN * BNF * NCHUNK, K2THR>>>(l, outc, outg);
}